// round 12
// baseline (speedup 1.0000x reference)
#include <cuda_runtime.h>

#define NN 4096
#define DIM 64
#define INF_V 1e10f
#define NBLK 32           // bands (128 rows each); warp w owns bands 2w (A) and 2w+1 (B)
#define NWARP 16
#define NTILE 1024        // tile-columns (4 cols each)
#define LAGT 34           // stream B trails stream A by this many tile-steps
#define LOG2E 1.4426950408889634f
#define LN2   0.6931471805599453f

__device__ float g_D[(size_t)NN * NN];    // cost matrix, PRE-SCALED by log2(e)
__device__ float g_xn[NN];
__device__ float g_yn[NN];
__device__ float g_bnd[NBLK][NN];         // boundary rows (only odd bands used)
__device__ int   g_prog[NBLK];            // tiles published per band

// ---------------- norms ----------------
__global__ void norms_kernel(const float* __restrict__ x, const float* __restrict__ y) {
    int w = (blockIdx.x * blockDim.x + threadIdx.x) >> 5;
    int lane = threadIdx.x & 31;
    if (w >= 2 * NN) return;
    const float* src = (w < NN) ? x : y;
    int row = (w < NN) ? w : w - NN;
    float a = src[row * DIM + lane];
    float b = src[row * DIM + 32 + lane];
    float s = a * a + b * b;
    #pragma unroll
    for (int o = 16; o; o >>= 1) s += __shfl_xor_sync(0xffffffffu, s, o);
    if (lane == 0) { if (w < NN) g_xn[row] = s; else g_yn[row] = s; }
}

// ---------------- D2 = (|x|^2 + |y|^2 - 2 x.y) * log2(e) ----------------
__global__ void dmat_kernel(const float* __restrict__ x, const float* __restrict__ y) {
    __shared__ float xs[64][65];
    __shared__ float ys[64][65];
    int tx = threadIdx.x, ty = threadIdx.y;
    int tid = ty * 16 + tx;
    int rb = blockIdx.y * 64, cb = blockIdx.x * 64;

    for (int i = tid; i < 64 * 64; i += 256) {
        int rr = i >> 6, kk = i & 63;
        xs[rr][kk] = x[(rb + rr) * DIM + kk];
        ys[rr][kk] = y[(cb + rr) * DIM + kk];
    }
    __syncthreads();

    float acc[4][4] = {};
    #pragma unroll
    for (int k = 0; k < 64; k++) {
        float xv[4], yv[4];
        #pragma unroll
        for (int i = 0; i < 4; i++) xv[i] = xs[ty + 16 * i][k];
        #pragma unroll
        for (int j = 0; j < 4; j++) yv[j] = ys[tx + 16 * j][k];
        #pragma unroll
        for (int i = 0; i < 4; i++)
            #pragma unroll
            for (int j = 0; j < 4; j++)
                acc[i][j] += xv[i] * yv[j];
    }

    #pragma unroll
    for (int i = 0; i < 4; i++) {
        int r = rb + ty + 16 * i;
        float xnr = g_xn[r];
        #pragma unroll
        for (int j = 0; j < 4; j++) {
            int c = cb + tx + 16 * j;
            g_D[(size_t)r * NN + c] = (xnr + g_yn[c] - 2.0f * acc[i][j]) * LOG2E;
        }
    }
}

// ---------------- reset progress flags ----------------
__global__ void init_kernel() {
    if (threadIdx.x < NBLK) g_prog[threadIdx.x] = 0;
}

// ---------------- DP: dual-band warps, interleaved 4x4 wavefront tiles ------
__device__ __forceinline__ int ld_acq(const int* p) {
    int v;
    asm volatile("ld.acquire.gpu.u32 %0, [%1];" : "=r"(v) : "l"(p) : "memory");
    return v;
}
__device__ __forceinline__ void st_rel(int* p, int v) {
    asm volatile("st.release.gpu.u32 [%0], %1;" :: "l"(p), "r"(v) : "memory");
}
__device__ __forceinline__ float ex2(float x) {
    float r; asm("ex2.approx.f32 %0, %1;" : "=f"(r) : "f"(x)); return r;
}
__device__ __forceinline__ float lg2(float x) {
    float r; asm("lg2.approx.f32 %0, %1;" : "=f"(r) : "f"(x)); return r;
}

// base-2 softmin cell, 3 MUFU: the min's exp term is exactly 1.
#define CELL(nv, u, d, l, cost) do {                                   \
    float p_ = fminf((u), (d));                                        \
    float q_ = fmaxf((u), (d));                                        \
    float m_ = fminf(p_, (l));                                         \
    float md_ = fmaxf(p_, fminf(q_, (l)));                             \
    float mx_ = fmaxf(q_, (l));                                        \
    float s_ = 1.0f + ex2(m_ - md_) + ex2(m_ - mx_);                   \
    (nv) = (cost) + m_ - lg2(s_);                                      \
} while (0)

__global__ void __launch_bounds__(32, 1) dp_kernel(float* __restrict__ out) {
    __shared__ float topb[18];        // cross-warp boundary window for stream A
    __shared__ float4 ring[64];       // warp-internal A->B boundary ring (per tile)

    const int w = blockIdx.x;
    const int L = threadIdx.x;
    const int bA = 2 * w;
    const int bB = bA + 1;
    const int rA0 = bA * 128 + 4 * L;
    const int rB0 = bB * 128 + 4 * L;
    const float4* __restrict__ Ar0 = (const float4*)(g_D + (size_t)(rA0 + 0) * NN);
    const float4* __restrict__ Ar1 = (const float4*)(g_D + (size_t)(rA0 + 1) * NN);
    const float4* __restrict__ Ar2 = (const float4*)(g_D + (size_t)(rA0 + 2) * NN);
    const float4* __restrict__ Ar3 = (const float4*)(g_D + (size_t)(rA0 + 3) * NN);
    const float4* __restrict__ Br0 = (const float4*)(g_D + (size_t)(rB0 + 0) * NN);
    const float4* __restrict__ Br1 = (const float4*)(g_D + (size_t)(rB0 + 1) * NN);
    const float4* __restrict__ Br2 = (const float4*)(g_D + (size_t)(rB0 + 2) * NN);
    const float4* __restrict__ Br3 = (const float4*)(g_D + (size_t)(rB0 + 3) * NN);
    float* mybndB = g_bnd[bB];
    const float* upbnd = (w > 0) ? g_bnd[bA - 1] : (const float*)0;

    // stream A state
    float alft0 = INF_V, alft1 = INF_V, alft2 = INF_V, alft3 = INF_V;
    float abot0 = INF_V, abot1 = INF_V, abot2 = INF_V, abot3 = INF_V;
    float adg = INF_V;
    // stream B state
    float blft0 = INF_V, blft1 = INF_V, blft2 = INF_V, blft3 = INF_V;
    float bbot0 = INF_V, bbot1 = INF_V, bbot2 = INF_V, bbot3 = INF_V;
    float bdg = INF_V;

    float4 a0 = __ldg(Ar0), a1 = __ldg(Ar1), a2 = __ldg(Ar2), a3 = __ldg(Ar3);
    float4 b0 = __ldg(Br0), b1 = __ldg(Br1), b2 = __ldg(Br2), b3 = __ldg(Br3);

    const int TT = NTILE + LAGT + 31;
    #pragma unroll 1
    for (int tau = 0; tau < TT; tau++) {
        const int jA = tau - L;                   // stream A tile-column
        const int jB = tau - LAGT - L;            // stream B tile-column

        __syncwarp();                             // ring write->read visibility

        // ---- stream A cross-warp staging (R4 protocol, verbatim) ----
        if (w > 0 && tau < NTILE && (tau & 3) == 0) {
            if (L == 0) { while (ld_acq(&g_prog[bA - 1]) < tau + 4) { } }
            __syncwarp();
            if (L < 17) {
                int col = 4 * tau - 1 + L;
                topb[L] = (col >= 0) ? __ldcg(&upbnd[col]) : INF_V;
            }
            __syncwarp();
        }

        // ---- prefetch next tile costs (both streams) ----
        int jan = jA + 1; if (jan < 0) jan = 0; if (jan > NTILE - 1) jan = NTILE - 1;
        int jbn = jB + 1; if (jbn < 0) jbn = 0; if (jbn > NTILE - 1) jbn = NTILE - 1;
        float4 pa0 = __ldg(Ar0 + jan), pa1 = __ldg(Ar1 + jan);
        float4 pa2 = __ldg(Ar2 + jan), pa3 = __ldg(Ar3 + jan);
        float4 pb0 = __ldg(Br0 + jbn), pb1 = __ldg(Br1 + jbn);
        float4 pb2 = __ldg(Br2 + jbn), pb3 = __ldg(Br3 + jbn);

        // ---- top handoffs ----
        float at0 = __shfl_up_sync(0xffffffffu, abot0, 1);
        float at1 = __shfl_up_sync(0xffffffffu, abot1, 1);
        float at2 = __shfl_up_sync(0xffffffffu, abot2, 1);
        float at3 = __shfl_up_sync(0xffffffffu, abot3, 1);
        float bt0 = __shfl_up_sync(0xffffffffu, bbot0, 1);
        float bt1 = __shfl_up_sync(0xffffffffu, bbot1, 1);
        float bt2 = __shfl_up_sync(0xffffffffu, bbot2, 1);
        float bt3 = __shfl_up_sync(0xffffffffu, bbot3, 1);

        // stream A lane-0 edge (cross-warp window / b==0 init)
        if (L == 0) {
            if (w == 0) {
                at0 = at1 = at2 = at3 = INF_V;
                adg = (tau == 0) ? 0.0f : INF_V;
            } else {
                int p = (tau & 3) * 4;
                adg = topb[p];
                at0 = topb[p + 1]; at1 = topb[p + 2];
                at2 = topb[p + 3]; at3 = topb[p + 4];
            }
            // stream B lane-0 edge from the smem ring (band A's bottom rows)
            int jB0 = tau - LAGT;
            if (jB0 >= 0) {
                float4 cur = ring[jB0 & 63];
                bdg = (jB0 >= 1) ? ring[(jB0 - 1) & 63].w : INF_V;
                bt0 = cur.x; bt1 = cur.y; bt2 = cur.z; bt3 = cur.w;
            }
        }
        adg = (jA == 0 && L > 0) ? INF_V : adg;
        bdg = (jB == 0) ? INF_V : bdg;            // dp[.][-1] = INF (B rows never row 0)

        const bool actA = (jA >= 0) && (jA < NTILE);
        const bool actB = (jB >= 0) && (jB < NTILE);

        // ---- two independent 4x4 tiles, ranks interleaved for ILP ----
        float A00,A01,A02,A03,A10,A11,A12,A13,A20,A21,A22,A23,A30,A31,A32,A33;
        float B00,B01,B02,B03,B10,B11,B12,B13,B20,B21,B22,B23,B30,B31,B32,B33;
        // rank 0
        CELL(A00, at0, adg,  alft0, a0.x);
        CELL(B00, bt0, bdg,  blft0, b0.x);
        // rank 1
        CELL(A01, at1, at0,  A00,  a0.y);
        CELL(B01, bt1, bt0,  B00,  b0.y);
        CELL(A10, A00, alft0, alft1, a1.x);
        CELL(B10, B00, blft0, blft1, b1.x);
        // rank 2
        CELL(A02, at2, at1,  A01,  a0.z);
        CELL(B02, bt2, bt1,  B01,  b0.z);
        CELL(A11, A01, A00,  A10,  a1.y);
        CELL(B11, B01, B00,  B10,  b1.y);
        CELL(A20, A10, alft1, alft2, a2.x);
        CELL(B20, B10, blft1, blft2, b2.x);
        // rank 3
        CELL(A03, at3, at2,  A02,  a0.w);
        CELL(B03, bt3, bt2,  B02,  b0.w);
        CELL(A12, A02, A01,  A11,  a1.z);
        CELL(B12, B02, B01,  B11,  b1.z);
        CELL(A21, A11, A10,  A20,  a2.y);
        CELL(B21, B11, B10,  B20,  b2.y);
        CELL(A30, A20, alft2, alft3, a3.x);
        CELL(B30, B20, blft2, blft3, b3.x);
        // rank 4
        CELL(A13, A03, A02,  A12,  a1.w);
        CELL(B13, B03, B02,  B12,  b1.w);
        CELL(A22, A12, A11,  A21,  a2.z);
        CELL(B22, B12, B11,  B21,  b2.z);
        CELL(A31, A21, A20,  A30,  a3.y);
        CELL(B31, B21, B20,  B30,  b3.y);
        // rank 5
        CELL(A23, A13, A12,  A22,  a2.w);
        CELL(B23, B13, B12,  B22,  b2.w);
        CELL(A32, A22, A21,  A31,  a3.z);
        CELL(B32, B22, B21,  B31,  b3.z);
        // rank 6
        CELL(A33, A23, A22,  A32,  a3.w);
        CELL(B33, B23, B22,  B32,  b3.w);

        // ---- commit (select, no divergence) ----
        alft0 = actA ? A03 : alft0; alft1 = actA ? A13 : alft1;
        alft2 = actA ? A23 : alft2; alft3 = actA ? A33 : alft3;
        abot0 = actA ? A30 : abot0; abot1 = actA ? A31 : abot1;
        abot2 = actA ? A32 : abot2; abot3 = actA ? A33 : abot3;
        blft0 = actB ? B03 : blft0; blft1 = actB ? B13 : blft1;
        blft2 = actB ? B23 : blft2; blft3 = actB ? B33 : blft3;
        bbot0 = actB ? B30 : bbot0; bbot1 = actB ? B31 : bbot1;
        bbot2 = actB ? B32 : bbot2; bbot3 = actB ? B33 : bbot3;

        if (L == 31) {
            if (actA) ring[jA & 63] = make_float4(abot0, abot1, abot2, abot3);
            if (actB) {
                *(float4*)&mybndB[4 * jB] = make_float4(bbot0, bbot1, bbot2, bbot3);
                if ((jB & 3) == 3 && bB < NBLK - 1)
                    st_rel(&g_prog[bB], jB + 1);
            }
        }
        adg = at3; bdg = bt3;

        a0 = pa0; a1 = pa1; a2 = pa2; a3 = pa3;
        b0 = pb0; b1 = pb1; b2 = pb2; b3 = pb3;
    }

    if (w == NWARP - 1 && L == 31) out[0] = blft3 * LN2;   // dp[4096][4096]
}

extern "C" void kernel_launch(void* const* d_in, const int* in_sizes, int n_in,
                              void* d_out, int out_size) {
    const float* x = (const float*)d_in[0];
    const float* y = (const float*)d_in[1];
    float* out = (float*)d_out;

    norms_kernel<<<(2 * NN * 32) / 256, 256>>>(x, y);
    dim3 gD(NN / 64, NN / 64);
    dim3 bD(16, 16);
    dmat_kernel<<<gD, bD>>>(x, y);
    init_kernel<<<1, NBLK>>>();
    dp_kernel<<<NWARP, 32>>>(out);
}